// round 3
// baseline (speedup 1.0000x reference)
#include <cuda_runtime.h>
#include <cuda_bf16.h>
#include <math.h>

#define BB   4096
#define NN   32
#define DIN  256
#define HH   256
#define RR   3
#define VDECAY 0.7f

#define BT   16                 // batches per fgemm block
#define NBT  (BB / BT)          // 256 batch tiles

// ---------------- device scratch (no runtime allocation allowed) ----------------
// W_f transposed to [r][h][g] (g contiguous)
__device__ float g_WfT2[RR * HH * HH];
// Gate weights transposed: [gate][k][g], gate 0=i,1=o,2=u
__device__ float g_WgT[3 * 512 * HH];
// combined [b][512] = [input_vec | child_h_sum]
__device__ float g_comb[BB * 512];
// per-relation partial child_c_sum [r][b][g]  (deterministic, no atomics)
__device__ float g_csum3[RR * BB * HH];

// ---------------- f32x2 helpers ----------------
__device__ __forceinline__ unsigned long long pk2(float a, float b) {
    unsigned long long r;
    asm("mov.b64 %0, {%1, %2};" : "=l"(r) : "f"(a), "f"(b));
    return r;
}
__device__ __forceinline__ float2 upk2(unsigned long long v) {
    float2 r;
    asm("mov.b64 {%0, %1}, %2;" : "=f"(r.x), "=f"(r.y) : "l"(v));
    return r;
}
__device__ __forceinline__ unsigned long long fma2_(unsigned long long a,
                                                    unsigned long long b,
                                                    unsigned long long c) {
    unsigned long long d;
    asm("fma.rn.f32x2 %0, %1, %2, %3;" : "=l"(d) : "l"(a), "l"(b), "l"(c));
    return d;
}
__device__ __forceinline__ void cpa16(void* smem_dst, const void* gsrc) {
    unsigned s = (unsigned)__cvta_generic_to_shared(smem_dst);
    asm volatile("cp.async.ca.shared.global [%0], [%1], 16;" :: "r"(s), "l"(gsrc) : "memory");
}
__device__ __forceinline__ void cpa_commit() {
    asm volatile("cp.async.commit_group;" ::: "memory");
}
template <int N>
__device__ __forceinline__ void cpa_wait() {
    asm volatile("cp.async.wait_group %0;" :: "n"(N) : "memory");
}

// ---------------- prep: transposes ----------------
__global__ void prep_kernel(const float* __restrict__ Wf,
                            const float* __restrict__ Wi,
                            const float* __restrict__ Wo,
                            const float* __restrict__ Wu) {
    int idx = blockIdx.x * blockDim.x + threadIdx.x;
    const int NF = RR * HH * HH;        // 196608
    const int NG = 3 * 512 * HH;        // 393216
    if (idx < NF) {
        // g_WfT2[(r*256 + h)*256 + g] = Wf[(r*256 + g)*256 + h]
        int g = idx & 255;
        int h = (idx >> 8) & 255;
        int r = idx >> 16;
        g_WfT2[idx] = Wf[(r * HH + g) * HH + h];
    } else if (idx < NF + NG) {
        int j = idx - NF;
        int g = j & 255;
        int t = j >> 8;
        int k = t & 511;
        int gate = t >> 9;
        const float* W = (gate == 0) ? Wi : ((gate == 1) ? Wo : Wu);
        g_WgT[j] = W[g * 512 + k];
    }
}

// ---------------- kernel B: attention + child_h_sum + combined ----------------
#define CHS 260
__global__ __launch_bounds__(256) void attn_kernel(
    const float* __restrict__ input_vec,
    const float* __restrict__ child_h,
    const int*   __restrict__ relation_ids,
    const int*   __restrict__ virtual_mask,
    const float* __restrict__ rel_emb,
    const float* __restrict__ w_att,
    const float* __restrict__ b_att)
{
    __shared__ float sh_ch[NN * CHS];
    __shared__ int   sh_rid[NN];
    __shared__ float sh_decay[NN], sh_score[NN], sh_attn[NN];

    const int b    = blockIdx.x;
    const int tid  = threadIdx.x;
    const int lane = tid & 31;
    const int warp = tid >> 5;

    if (tid < NN) {
        sh_rid[tid]   = relation_ids[b * NN + tid];
        sh_decay[tid] = virtual_mask[b * NN + tid] ? VDECAY : 1.0f;
    }
    __syncthreads();

    {
        const float* chb = child_h + (size_t)b * NN * HH;
        for (int idx = tid; idx < NN * HH; idx += 256) {
            int n = idx >> 8;
            int h = idx & 255;
            sh_ch[n * CHS + h] = chb[n * HH + h] * sh_decay[n];
        }
    }
    __syncthreads();

    {
        float batt = b_att[0];
        #pragma unroll
        for (int c = 0; c < 4; c++) {
            int p = warp * 4 + c;
            int r = sh_rid[p];
            float s = 0.0f;
            #pragma unroll
            for (int j = 0; j < 8; j++) {
                int h = j * 32 + lane;
                s = fmaf(rel_emb[r * HH + h] + sh_ch[p * CHS + h], w_att[h], s);
            }
            #pragma unroll
            for (int off = 16; off; off >>= 1)
                s += __shfl_xor_sync(0xffffffffu, s, off);
            if (lane == 0) sh_score[p] = s + batt;
        }
    }
    __syncthreads();

    if (warp == 0) {
        float v = sh_score[lane];
        float m = v;
        #pragma unroll
        for (int off = 16; off; off >>= 1)
            m = fmaxf(m, __shfl_xor_sync(0xffffffffu, m, off));
        float e = expf(v - m);
        float s = e;
        #pragma unroll
        for (int off = 16; off; off >>= 1)
            s += __shfl_xor_sync(0xffffffffu, s, off);
        sh_attn[lane] = e / s;
    }
    __syncthreads();

    const int g = tid;
    float hs = 0.0f;
    #pragma unroll
    for (int p = 0; p < NN; p++)
        hs = fmaf(sh_attn[p], sh_ch[p * CHS + g], hs);
    g_comb[b * 512 + 256 + g] = hs;
    g_comb[b * 512 + g]       = input_vec[b * DIN + g];
}

// ---------------- kernel C: relation-grouped f GEMM + child_c_sum partial ----
// grid (NBT, RR, 2). block 256 = 128 g x 2 half(child split).
// dynamic smem layout (bytes):
//   [0, 131072)        shW  float2[128 h2][128 g]
//   [131072, 164352)   shC  2 x 16 child x 130 float2 (child stride 1040B)
//   [164352, 180736)   shCS float[2][BT][128]
//   [180736, 182784)   shList int[512]
#define SMC_W    0
#define SMC_C    131072
#define SMC_CBUF 16640
#define SMC_CS   164352
#define SMC_LIST 180736
#define SMC_TOT  182784

__global__ __launch_bounds__(256) void fgemm_kernel(
    const float* __restrict__ child_h,
    const float* __restrict__ child_c,
    const int*   __restrict__ relation_ids,
    const int*   __restrict__ virtual_mask,
    const float* __restrict__ b_f)
{
    extern __shared__ char smc[];
    float2* shW   = (float2*)(smc + SMC_W);
    float2* shC   = (float2*)(smc + SMC_C);
    float*  shCS  = (float*)(smc + SMC_CS);
    int*    shList = (int*)(smc + SMC_LIST);
    __shared__ int shCnt;

    const int tid  = threadIdx.x;
    const int gl   = tid & 127;
    const int half = tid >> 7;
    const int b0   = blockIdx.x * BT;
    const int r    = blockIdx.y;
    const int g0   = blockIdx.z * 128;

    if (tid == 0) shCnt = 0;
    for (int i = tid; i < 2 * BT * 128; i += 256) shCS[i] = 0.0f;

    // ---- stage W slice [256 h][128 g] as interleaved (h,h+1) float2 pairs ----
    for (int i2 = tid; i2 < 4096; i2 += 256) {
        int h2  = i2 >> 5;
        int glq = (i2 & 31) * 4;
        const float4 a4 = *(const float4*)&g_WfT2[(r * 256 + 2 * h2) * 256 + g0 + glq];
        const float4 b4 = *(const float4*)&g_WfT2[(r * 256 + 2 * h2 + 1) * 256 + g0 + glq];
        shW[h2 * 128 + glq + 0] = make_float2(a4.x, b4.x);
        shW[h2 * 128 + glq + 1] = make_float2(a4.y, b4.y);
        shW[h2 * 128 + glq + 2] = make_float2(a4.z, b4.z);
        shW[h2 * 128 + glq + 3] = make_float2(a4.w, b4.w);
    }
    __syncthreads();

    // ---- build compacted child list for relation r ----
    for (int i = tid; i < BT * NN; i += 256) {
        int rid = relation_ids[b0 * NN + i];
        if (rid == r) {
            int v = virtual_mask[b0 * NN + i] ? 1 : 0;
            int pos = atomicAdd(&shCnt, 1);
            shList[pos] = (i << 1) | v;
        }
    }
    __syncthreads();
    const int count = shCnt;
    const int tiles = (count + 15) >> 4;
    const float bf  = b_f[r * HH + g0 + gl];

    // ---- stage helper (cp.async, raw child_h; decay factored out) ----
    auto stage = [&](int tj, int buf) {
        for (int i = tid; i < 16 * 64; i += 256) {
            int cl   = i >> 6;
            int q    = i & 63;
            int slot = tj * 16 + cl;
            if (slot < count) {
                int e = shList[slot];
                int idx10 = e >> 1;
                const float* src = child_h +
                    ((size_t)(b0 + (idx10 >> 5)) * NN + (idx10 & 31)) * HH + q * 4;
                char* dst = smc + SMC_C + buf * SMC_CBUF + cl * 1040 + q * 16;
                cpa16(dst, src);
            }
        }
        cpa_commit();
    };

    if (tiles > 0) stage(0, 0);

    #pragma unroll 1
    for (int tj = 0; tj < tiles; tj++) {
        int buf = tj & 1;
        if (tj + 1 < tiles) stage(tj + 1, buf ^ 1);
        else cpa_commit();   // keep group count in lockstep
        cpa_wait<1>();
        __syncthreads();

        // prefetch cc + list entries for this thread's 8 children
        int   ev[8];
        float ccv[8];
        #pragma unroll
        for (int c8 = 0; c8 < 8; c8++) {
            int slot = tj * 16 + half * 8 + c8;
            if (slot < count) {
                int e = shList[slot];
                ev[c8] = e;
                int idx10 = e >> 1;
                ccv[c8] = child_c[((size_t)(b0 + (idx10 >> 5)) * NN + (idx10 & 31)) * HH + g0 + gl];
            } else {
                ev[c8] = -1;
                ccv[c8] = 0.0f;
            }
        }

        // ---- packed matvec: 8 children x 256 h ----
        unsigned long long acc[8];
        #pragma unroll
        for (int c8 = 0; c8 < 8; c8++) acc[c8] = 0ull;

        #pragma unroll 1
        for (int hb = 0; hb < 8; hb++) {
            unsigned long long wv[16];
            #pragma unroll
            for (int j = 0; j < 16; j++)
                wv[j] = *(const unsigned long long*)&shW[(hb * 16 + j) * 128 + gl];
            #pragma unroll
            for (int c8 = 0; c8 < 8; c8++) {
                const ulonglong2* cp = (const ulonglong2*)
                    (smc + SMC_C + buf * SMC_CBUF + (half * 8 + c8) * 1040 + hb * 128);
                #pragma unroll
                for (int j2 = 0; j2 < 8; j2++) {
                    ulonglong2 cv = cp[j2];
                    acc[c8] = fma2_(cv.x, wv[2 * j2], acc[c8]);
                    acc[c8] = fma2_(cv.y, wv[2 * j2 + 1], acc[c8]);
                }
            }
        }

        // ---- fold: cs += (f*d + bf) * (cc*d) ----
        #pragma unroll
        for (int c8 = 0; c8 < 8; c8++) {
            if (ev[c8] >= 0) {
                float2 p = upk2(acc[c8]);
                float d  = (ev[c8] & 1) ? VDECAY : 1.0f;
                float f  = (p.x + p.y) * d;
                int bl   = (ev[c8] >> 1) >> 5;
                shCS[(half * BT + bl) * 128 + gl] += (f + bf) * (ccv[c8] * d);
            }
        }
        __syncthreads();
    }
    cpa_wait<0>();

    // ---- write per-relation partial csum ----
    for (int i = tid; i < BT * 128; i += 256) {
        int bl  = i >> 7;
        int gl2 = i & 127;
        g_csum3[((size_t)r * BB + b0 + bl) * HH + g0 + gl2] =
            shCS[bl * 128 + gl2] + shCS[(BT + bl) * 128 + gl2];
    }
}

// ---------------- kernel D: gate GEMM (f32x2 over batch pairs) + epilogue ----
__global__ __launch_bounds__(256) void gates_kernel(
    const float* __restrict__ b_i,
    const float* __restrict__ b_o,
    const float* __restrict__ b_u,
    float* __restrict__ out)
{
    __shared__ float sh_comb[16 * 512];
    const int b0  = blockIdx.x * 16;
    const int tid = threadIdx.x;

    for (int idx = tid; idx < 16 * 512; idx += 256)
        sh_comb[idx] = g_comb[b0 * 512 + idx];
    __syncthreads();

    const int g = tid;
    unsigned long long ai2[8], ao2[8], au2[8];
    #pragma unroll
    for (int mp = 0; mp < 8; mp++) { ai2[mp] = 0ull; ao2[mp] = 0ull; au2[mp] = 0ull; }

    const float* wi = g_WgT;
    const float* wo = g_WgT + 512 * HH;
    const float* wu = g_WgT + 2 * 512 * HH;

    #pragma unroll 1
    for (int k4 = 0; k4 < 128; k4++) {
        int k = k4 * 4;
        float wi0 = wi[(k + 0) * HH + g], wi1 = wi[(k + 1) * HH + g];
        float wi2 = wi[(k + 2) * HH + g], wi3 = wi[(k + 3) * HH + g];
        float wo0 = wo[(k + 0) * HH + g], wo1 = wo[(k + 1) * HH + g];
        float wo2 = wo[(k + 2) * HH + g], wo3 = wo[(k + 3) * HH + g];
        float wu0 = wu[(k + 0) * HH + g], wu1 = wu[(k + 1) * HH + g];
        float wu2 = wu[(k + 2) * HH + g], wu3 = wu[(k + 3) * HH + g];
        unsigned long long di0 = pk2(wi0, wi0), di1 = pk2(wi1, wi1);
        unsigned long long di2 = pk2(wi2, wi2), di3 = pk2(wi3, wi3);
        unsigned long long do0 = pk2(wo0, wo0), do1 = pk2(wo1, wo1);
        unsigned long long do2 = pk2(wo2, wo2), do3 = pk2(wo3, wo3);
        unsigned long long du0 = pk2(wu0, wu0), du1 = pk2(wu1, wu1);
        unsigned long long du2 = pk2(wu2, wu2), du3 = pk2(wu3, wu3);
        #pragma unroll
        for (int mp = 0; mp < 8; mp++) {
            const float4 cA = *(const float4*)&sh_comb[(2 * mp) * 512 + k];
            const float4 cB = *(const float4*)&sh_comb[(2 * mp + 1) * 512 + k];
            unsigned long long c0 = pk2(cA.x, cB.x);
            unsigned long long c1 = pk2(cA.y, cB.y);
            unsigned long long c2 = pk2(cA.z, cB.z);
            unsigned long long c3 = pk2(cA.w, cB.w);
            ai2[mp] = fma2_(c0, di0, ai2[mp]); ai2[mp] = fma2_(c1, di1, ai2[mp]);
            ai2[mp] = fma2_(c2, di2, ai2[mp]); ai2[mp] = fma2_(c3, di3, ai2[mp]);
            ao2[mp] = fma2_(c0, do0, ao2[mp]); ao2[mp] = fma2_(c1, do1, ao2[mp]);
            ao2[mp] = fma2_(c2, do2, ao2[mp]); ao2[mp] = fma2_(c3, do3, ao2[mp]);
            au2[mp] = fma2_(c0, du0, au2[mp]); au2[mp] = fma2_(c1, du1, au2[mp]);
            au2[mp] = fma2_(c2, du2, au2[mp]); au2[mp] = fma2_(c3, du3, au2[mp]);
        }
    }

    const float biv = b_i[g], bov = b_o[g], buv = b_u[g];
    #pragma unroll
    for (int mp = 0; mp < 8; mp++) {
        float2 fi = upk2(ai2[mp]);
        float2 fo = upk2(ao2[mp]);
        float2 fu = upk2(au2[mp]);
        #pragma unroll
        for (int s = 0; s < 2; s++) {
            int b = b0 + 2 * mp + s;
            float av = s ? fi.y : fi.x;
            float bv = s ? fo.y : fo.x;
            float cv = s ? fu.y : fu.x;
            float cs = g_csum3[(size_t)b * HH + g]
                     + g_csum3[(size_t)(BB + b) * HH + g]
                     + g_csum3[(size_t)(2 * BB + b) * HH + g];
            float iv = 1.0f / (1.0f + expf(-(av + biv)));
            float ov = 1.0f / (1.0f + expf(-(bv + bov)));
            float uv = tanhf(cv + buv);
            float c  = fmaf(iv, uv, cs);
            float h  = ov * tanhf(c);
            out[(size_t)b * HH + g]           = h;   // h first
            out[(size_t)(BB + b) * HH + g]    = c;   // then c
        }
    }
}

// ---------------- launch ----------------
extern "C" void kernel_launch(void* const* d_in, const int* in_sizes, int n_in,
                              void* d_out, int out_size) {
    const float* input_vec = (const float*)d_in[0];
    const float* child_h   = (const float*)d_in[1];
    const float* child_c   = (const float*)d_in[2];
    const int*   rid       = (const int*)d_in[3];
    const int*   vmask     = (const int*)d_in[4];
    const float* rel_emb   = (const float*)d_in[5];
    const float* W_i = (const float*)d_in[6];
    const float* b_i = (const float*)d_in[7];
    const float* W_f = (const float*)d_in[8];
    const float* b_f = (const float*)d_in[9];
    const float* W_o = (const float*)d_in[10];
    const float* b_o = (const float*)d_in[11];
    const float* W_u = (const float*)d_in[12];
    const float* b_u = (const float*)d_in[13];
    const float* w_att = (const float*)d_in[14];
    const float* b_att = (const float*)d_in[15];
    float* out = (float*)d_out;

    static int configured = 0;
    if (!configured) {
        cudaFuncSetAttribute(fgemm_kernel, cudaFuncAttributeMaxDynamicSharedMemorySize, SMC_TOT);
        configured = 1;
    }

    prep_kernel<<<2304, 256>>>(W_f, W_i, W_o, W_u);
    attn_kernel<<<BB, 256>>>(input_vec, child_h, rid, vmask, rel_emb, w_att, b_att);
    dim3 fgrid(NBT, RR, 2);
    fgemm_kernel<<<fgrid, 256, SMC_TOT>>>(child_h, child_c, rid, vmask, b_f);
    gates_kernel<<<BB / 16, 256>>>(b_i, b_o, b_u, out);
}